// round 12
// baseline (speedup 1.0000x reference)
#include <cuda_runtime.h>
#include <cuda_bf16.h>
#include <cstdint>

typedef unsigned long long ull;

#define BB 1024
#define TT 128
#define DD 13
#define HH 512
#define CC 9
#define BT (BB*TT)
#define EPSF 1e-5f
#define NSLOT 64

#define PM 128
#define PN 256
#define PK 32
#define APAD 36
#define BPAD 260
#define PMMA_SMEM ((2*PM*APAD + 2*PK*BPAD)*4)

#define HP 260
#define RSMEM2 (2*16*HP*8)     // pingpong x 16 rows x HP packed u64 = 66560 B

#define CLUSTER_SYNC() do{ \
    asm volatile("barrier.cluster.arrive.aligned;" ::: "memory"); \
    asm volatile("barrier.cluster.wait.aligned;"   ::: "memory"); \
}while(0)

// ---------------- scratch (device globals) ----------------
__device__ float g_xn[BT*16];
__device__ float g_xK[BT*HH];
__device__ float g_z [BT*HH];
__device__ float g_o [BT*HH];
__device__ float g_psum[NSLOT*HH];
__device__ float g_psq [NSLOT*HH];
__device__ float g_mean[HH], g_rstd[HH], g_s[HH], g_c[HH];
__device__ __align__(16) unsigned g_W2hi[256*512];   // fragment-major bf16 hi (32-warp layout)
__device__ __align__(16) unsigned g_W2lo[256*512];   // lo residual
__device__ float g_Bt[512*1024];                     // tf32 BN-folded [Wk'|Wz'] as [k][n]
__device__ float g_bcat[1024];

// ---------------- helpers ----------------
__device__ __forceinline__ float tanh_a(float x){
    float r; asm("tanh.approx.f32 %0,%1;" : "=f"(r) : "f"(x)); return r;
}
__device__ __forceinline__ float sigm_a(float x){
    return fmaf(0.5f, tanh_a(0.5f*x), 0.5f);
}
__device__ __forceinline__ uint32_t cvt_tf32(float f){
    uint32_t u; asm("cvt.rna.tf32.f32 %0,%1;" : "=r"(u) : "f"(f)); return u;
}
__device__ __forceinline__ void cp16(uint32_t dst, const void* src){
    asm volatile("cp.async.ca.shared.global [%0],[%1],16;" :: "r"(dst), "l"(src));
}
__device__ __forceinline__ void mma_tf32(float* c, const uint32_t* a, const uint32_t* b){
    asm volatile("mma.sync.aligned.m16n8k8.row.col.f32.tf32.tf32.f32 "
        "{%0,%1,%2,%3},{%4,%5,%6,%7},{%8,%9},{%0,%1,%2,%3};"
        : "+f"(c[0]), "+f"(c[1]), "+f"(c[2]), "+f"(c[3])
        : "r"(a[0]), "r"(a[1]), "r"(a[2]), "r"(a[3]), "r"(b[0]), "r"(b[1]));
}
__device__ __forceinline__ void mma_bf16(float* c, const uint32_t* a, uint32_t b0, uint32_t b1){
    asm volatile("mma.sync.aligned.m16n8k16.row.col.f32.bf16.bf16.f32 "
        "{%0,%1,%2,%3},{%4,%5,%6,%7},{%8,%9},{%0,%1,%2,%3};"
        : "+f"(c[0]), "+f"(c[1]), "+f"(c[2]), "+f"(c[3])
        : "r"(a[0]), "r"(a[1]), "r"(a[2]), "r"(a[3]), "r"(b0), "r"(b1));
}

// ---------------- 1) input LayerNorm over D=13 ----------------
__global__ void k_ln(const float* __restrict__ x, const float* __restrict__ g,
                     const float* __restrict__ b){
    int m = blockIdx.x*blockDim.x + threadIdx.x;
    if (m >= BT) return;
    const float* r = x + m*DD;
    float s = 0.f;
    #pragma unroll
    for (int k=0;k<DD;k++) s += r[k];
    float mu = s * (1.f/DD);
    float v = 0.f;
    #pragma unroll
    for (int k=0;k<DD;k++){ float d = r[k]-mu; v += d*d; }
    float rs = rsqrtf(v*(1.f/DD) + EPSF);
    float* o = g_xn + m*16;
    #pragma unroll
    for (int k=0;k<DD;k++) o[k] = (r[k]-mu)*rs*g[k] + b[k];
    o[13]=0.f; o[14]=0.f; o[15]=0.f;
}

// ---------------- 2) layer-1 projections (K=13) ----------------
__global__ void __launch_bounds__(512) k_proj1(const float* __restrict__ WK, const float* __restrict__ bK,
                                               const float* __restrict__ WZ, const float* __restrict__ bZ){
    __shared__ float xt[64][16];
    int tid = threadIdx.x;
    int m0  = blockIdx.x*64;
    #pragma unroll
    for (int i=0;i<2;i++){
        int idx = tid + i*512;
        xt[idx>>4][idx&15] = g_xn[m0*16 + idx];
    }
    float wk[DD], wz[DD];
    #pragma unroll
    for (int i=0;i<DD;i++){ wk[i]=WK[tid*DD+i]; wz[i]=WZ[tid*DD+i]; }
    float bk = bK[tid], bz = bZ[tid];
    __syncthreads();
    for (int m=0;m<64;m++){
        float ak = bk, az = bz;
        #pragma unroll
        for (int i=0;i<DD;i++){ float xv = xt[m][i]; ak = fmaf(xv,wk[i],ak); az = fmaf(xv,wz[i],az); }
        g_xK[(m0+m)*HH + tid] = ak;
        g_z [(m0+m)*HH + tid] = tanh_a(az);
    }
}

// ---------------- 3) pack recurrence W: bf16 hi/lo, 32-warp fragment-major ----------------
// kp = c*16 + kt*8 + p*4 + tig ; j = w*16 + nt*8 + g  (w 0..31, nt 0..1)
// u32 index F = (((c*2+kt)*32 + w)*32 + g*4+tig)*4 + p*2 + nt
__global__ void k_packW2(const float* __restrict__ W){
    int kp = blockIdx.x;      // 0..255
    int j  = threadIdx.x;     // 0..511
    float2 wv = *(const float2*)&W[j*HH + 2*kp];
    __nv_bfloat16 h0 = __float2bfloat16(wv.x);
    __nv_bfloat16 h1 = __float2bfloat16(wv.y);
    __nv_bfloat16 l0 = __float2bfloat16(wv.x - __bfloat162float(h0));
    __nv_bfloat16 l1 = __float2bfloat16(wv.y - __bfloat162float(h1));
    int c = kp>>4, r = kp&15;
    int kt = r>>3, r2 = r&7;
    int p = r2>>2, tig = r2&3;
    int w = j>>4, nt = (j>>3)&1, g = j&7;
    int F = ((((c*2+kt)*32 + w)*32 + g*4 + tig)<<2) + p*2 + nt;
    __nv_bfloat162 ph; ph.x = h0; ph.y = h1;
    __nv_bfloat162 pl; pl.x = l0; pl.y = l1;
    g_W2hi[F] = *(unsigned*)&ph;
    g_W2lo[F] = *(unsigned*)&pl;
}

// ---------------- 4) recurrence: bf16x2-split MMA, 16 warps, packed-u64 h ----------------
__global__ void __launch_bounds__(512,1) __cluster_dims__(2,1,1)
k_recur(const float* __restrict__ bh){
    extern __shared__ __align__(16) ull hl[];
    ull* Hp[2] = { hl, hl + 16*HP };

    const int tid  = threadIdx.x;
    const int wl   = tid >> 5;          // local warp 0..15
    const int lane = tid & 31;
    const int g    = lane >> 2;
    const int tig  = lane & 3;
    uint32_t rank; asm("mov.u32 %0,%%cluster_ctarank;" : "=r"(rank));
    const uint32_t peer = rank ^ 1u;
    const int w    = (int)rank*16 + wl;  // global warp 0..31 (16-col group)
    const int b0r  = (blockIdx.x>>1)*16;

    for (int i=tid;i<16*HP;i+=512) Hp[0][i] = 0ull;

    float2 bhp[2];
    #pragma unroll
    for (int nt=0;nt<2;nt++) bhp[nt] = *(const float2*)&bh[w*16 + nt*8 + 2*tig];

    float2 ssA[2], sqA[2];
    #pragma unroll
    for (int nt=0;nt<2;nt++){ ssA[nt]=make_float2(0.f,0.f); sqA[nt]=make_float2(0.f,0.f); }

    const uint4* __restrict__ GH = (const uint4*)g_W2hi;
    const uint4* __restrict__ GL = (const uint4*)g_W2lo;
    const int off0 = w*32 + lane;

    __syncthreads();
    CLUSTER_SYNC();

    int p = 0;
    for (int t=0;t<TT;t++){
        long base = ((long)b0r*TT + t)*HH;
        // prefetch gates (independent of h)
        float2 gkp[2][2], zzp[2][2];
        int doff[2][2];
        #pragma unroll
        for (int nt=0;nt<2;nt++){
            int col = w*16 + nt*8 + 2*tig;
            #pragma unroll
            for (int rr=0;rr<2;rr++){
                int row = g + rr*8;
                int d = row*(TT*HH) + col;
                doff[nt][rr] = d;
                gkp[nt][rr] = __ldcs((const float2*)(g_xK + base + d));
                zzp[nt][rr] = __ldcs((const float2*)(g_z  + base + d));
            }
        }

        float acc[2][4];
        #pragma unroll
        for (int nt=0;nt<2;nt++){ acc[nt][0]=0.f; acc[nt][1]=0.f; acc[nt][2]=0.f; acc[nt][3]=0.f; }

        const ull* hp = Hp[p];

        // prefetch W fragments, distance 2
        uint4 fh[2], fl[2];
        #pragma unroll
        for (int s=0;s<2;s++){
            fh[s] = __ldg(GH + s*1024 + off0);
            fl[s] = __ldg(GL + s*1024 + off0);
        }

        #pragma unroll 2
        for (int i=0;i<32;i++){
            int s = i & 1;
            uint4 FH = fh[s], FL = fl[s];
            if (i < 30){
                fh[s] = __ldg(GH + (i+2)*1024 + off0);
                fl[s] = __ldg(GL + (i+2)*1024 + off0);
            }
            int kpg = i*8;
            ull v0 = hp[ g   *HP + kpg + tig];
            ull v1 = hp[(g+8)*HP + kpg + tig];
            ull v2 = hp[ g   *HP + kpg + tig + 4];
            ull v3 = hp[(g+8)*HP + kpg + tig + 4];
            uint32_t ah[4], al[4];
            ah[0]=(uint32_t)v0; al[0]=(uint32_t)(v0>>32);
            ah[1]=(uint32_t)v1; al[1]=(uint32_t)(v1>>32);
            ah[2]=(uint32_t)v2; al[2]=(uint32_t)(v2>>32);
            ah[3]=(uint32_t)v3; al[3]=(uint32_t)(v3>>32);

            mma_bf16(acc[0], ah, FH.x, FH.z);
            mma_bf16(acc[0], ah, FL.x, FL.z);
            mma_bf16(acc[0], al, FH.x, FH.z);
            mma_bf16(acc[1], ah, FH.y, FH.w);
            mma_bf16(acc[1], ah, FL.y, FL.w);
            mma_bf16(acc[1], al, FH.y, FH.w);
        }

        // epilogue
        ull* Hn = Hp[1-p];
        uint32_t lHn = (uint32_t)__cvta_generic_to_shared(Hn);
        uint32_t rHn;
        asm("mapa.shared::cluster.u32 %0,%1,%2;" : "=r"(rHn) : "r"(lHn), "r"(peer));

        #pragma unroll
        for (int nt=0;nt<2;nt++){
            int col = w*16 + nt*8 + 2*tig;
            int kp  = col >> 1;
            #pragma unroll
            for (int rr=0;rr<2;rr++){
                int row = g + rr*8;
                float2 gk = gkp[nt][rr];
                float2 zz = zzp[nt][rr];
                ull hv = hp[row*HP + kp];
                unsigned uh = (uint32_t)hv, ul = (uint32_t)(hv>>32);
                __nv_bfloat162 bh2 = *(__nv_bfloat162*)&uh;
                __nv_bfloat162 bl2 = *(__nv_bfloat162*)&ul;
                float ho0 = __bfloat162float(bh2.x) + __bfloat162float(bl2.x);
                float ho1 = __bfloat162float(bh2.y) + __bfloat162float(bl2.y);
                float K0 = sigm_a(gk.x + acc[nt][rr*2+0] + bhp[nt].x);
                float K1 = sigm_a(gk.y + acc[nt][rr*2+1] + bhp[nt].y);
                float hn0 = tanh_a(fmaf(K0, ho0 - zz.x, zz.x));
                float hn1 = tanh_a(fmaf(K1, ho1 - zz.y, zz.y));
                float r0 = __uint_as_float(cvt_tf32(hn0));
                float r1 = __uint_as_float(cvt_tf32(hn1));
                __stcs((float2*)(g_o + base + doff[nt][rr]), make_float2(r0, r1));
                ssA[nt].x += r0;  ssA[nt].y += r1;
                sqA[nt].x = fmaf(r0, r0, sqA[nt].x);
                sqA[nt].y = fmaf(r1, r1, sqA[nt].y);
                __nv_bfloat162 ph2 = __floats2bfloat162_rn(hn0, hn1);
                float2 hf = __bfloat1622float2(ph2);
                __nv_bfloat162 pl2 = __floats2bfloat162_rn(hn0 - hf.x, hn1 - hf.y);
                ull v = (ull)(*(unsigned*)&ph2) | ((ull)(*(unsigned*)&pl2) << 32);
                int idx = row*HP + kp;
                Hn[idx] = v;
                asm volatile("st.shared::cluster.u64 [%0], %1;" :: "r"(rHn + (uint32_t)idx*8u), "l"(v));
            }
        }
        CLUSTER_SYNC();
        p ^= 1;
    }

    // stats: reduce over the 8 row-lanes (g = lane bits 2..4)
    #pragma unroll
    for (int nt=0;nt<2;nt++){
        #pragma unroll
        for (int o=4;o<=16;o<<=1){
            ssA[nt].x += __shfl_xor_sync(~0u, ssA[nt].x, o);
            ssA[nt].y += __shfl_xor_sync(~0u, ssA[nt].y, o);
            sqA[nt].x += __shfl_xor_sync(~0u, sqA[nt].x, o);
            sqA[nt].y += __shfl_xor_sync(~0u, sqA[nt].y, o);
        }
    }
    if (lane < 4){
        int slot = blockIdx.x >> 1;
        #pragma unroll
        for (int nt=0;nt<2;nt++){
            int col = w*16 + nt*8 + 2*lane;
            g_psum[slot*HH + col]     = ssA[nt].x;
            g_psum[slot*HH + col + 1] = ssA[nt].y;
            g_psq [slot*HH + col]     = sqA[nt].x;
            g_psq [slot*HH + col + 1] = sqA[nt].y;
        }
    }
}

// ---------------- 5) finalize BN stats + fold vectors ----------------
__global__ void k_statsfin(const float* __restrict__ bng, const float* __restrict__ bnb){
    int t = threadIdx.x;
    float s = 0.f, q = 0.f;
    for (int i=0;i<NSLOT;i++){ s += g_psum[i*HH + t]; q += g_psq[i*HH + t]; }
    float m  = s * (1.f/BT);
    float v  = q * (1.f/BT) - m*m;
    float rs = rsqrtf(v + EPSF);
    g_mean[t] = m;
    g_rstd[t] = rs;
    float sc = bng[t]*rs;
    g_s[t] = sc;
    g_c[t] = bnb[t] - m*sc;
}

// ---------------- 6) fold: biases + tf32 B pack ----------------
__global__ void k_fold2(const float* __restrict__ WK, const float* __restrict__ bK,
                        const float* __restrict__ WZ, const float* __restrict__ bZ){
    __shared__ float sk[8], sz[8];
    int j = blockIdx.x, t = threadIdx.x;
    float ck = 0.f, cz = 0.f;
    for (int k=t;k<HH;k+=256){
        float wkv = WK[j*HH+k];
        float wzv = WZ[j*HH+k];
        float c = g_c[k];
        float sv = g_s[k];
        ck = fmaf(wkv, c, ck);
        cz = fmaf(wzv, c, cz);
        g_Bt[k*1024 + j]       = __uint_as_float(cvt_tf32(wkv*sv));
        g_Bt[k*1024 + 512 + j] = __uint_as_float(cvt_tf32(wzv*sv));
    }
    #pragma unroll
    for (int o=16;o;o>>=1){ ck += __shfl_xor_sync(~0u,ck,o); cz += __shfl_xor_sync(~0u,cz,o); }
    if ((t&31)==0){ sk[t>>5]=ck; sz[t>>5]=cz; }
    __syncthreads();
    if (t==0){
        float a=0.f,b2=0.f;
        #pragma unroll
        for (int i=0;i<8;i++){ a+=sk[i]; b2+=sz[i]; }
        g_bcat[j]     = bK[j] + a;
        g_bcat[512+j] = bZ[j] + b2;
    }
}

// ---------------- 7) layer-2/3 projections: tf32 tensor GEMM (A pre-rounded) ----------------
__global__ void __launch_bounds__(256,1) k_pmma(){
    extern __shared__ float smem[];
    float* As[2] = { smem, smem + PM*APAD };
    float* Bs[2] = { smem + 2*PM*APAD, smem + 2*PM*APAD + PK*BPAD };
    uint32_t sA[2], sB[2];
    sA[0] = (uint32_t)__cvta_generic_to_shared(As[0]);
    sA[1] = (uint32_t)__cvta_generic_to_shared(As[1]);
    sB[0] = (uint32_t)__cvta_generic_to_shared(Bs[0]);
    sB[1] = (uint32_t)__cvta_generic_to_shared(Bs[1]);

    int tid = threadIdx.x;
    int wid = tid>>5, lane = tid&31;
    int g = lane>>2, tig = lane&3;
    int wm = wid & 1, wn = wid >> 1;
    int m0 = blockIdx.x * PM;
    int nb = blockIdx.y * PN;

    const float* Ag = g_o  + (size_t)m0*HH;
    const float* Bg = g_Bt + nb;

    float acc[4][8][4];
    #pragma unroll
    for (int mt=0;mt<4;mt++)
        #pragma unroll
        for (int nt=0;nt<8;nt++)
            #pragma unroll
            for (int i=0;i<4;i++) acc[mt][nt][i]=0.f;

    auto stage = [&](int c, int buf){
        #pragma unroll
        for (int i=0;i<4;i++){
            int u = i*256 + tid;
            int row = u>>3, seg = u&7;
            cp16(sA[buf] + (row*APAD + seg*4)*4, Ag + row*HH + c*PK + seg*4);
        }
        #pragma unroll
        for (int i=0;i<8;i++){
            int u = i*256 + tid;
            int row = u>>6, seg = u&63;
            cp16(sB[buf] + (row*BPAD + seg*4)*4, Bg + (size_t)(c*PK + row)*1024 + seg*4);
        }
        asm volatile("cp.async.commit_group;");
    };

    stage(0, 0);
    #pragma unroll 1
    for (int c=0;c<16;c++){
        int buf = c & 1;
        if (c < 15) stage(c+1, buf^1);
        if (c < 15) asm volatile("cp.async.wait_group 1;");
        else        asm volatile("cp.async.wait_group 0;");
        __syncthreads();

        #pragma unroll
        for (int k8=0;k8<4;k8++){
            int kk = k8*8;
            uint32_t a[4][4];
            #pragma unroll
            for (int mt=0;mt<4;mt++){
                const float* ap = &As[buf][(wm*64 + mt*16 + g)*APAD + kk + tig];
                a[mt][0] = __float_as_uint(ap[0]);
                a[mt][1] = __float_as_uint(ap[8*APAD]);
                a[mt][2] = __float_as_uint(ap[4]);
                a[mt][3] = __float_as_uint(ap[8*APAD+4]);
            }
            uint32_t b[8][2];
            #pragma unroll
            for (int nt=0;nt<8;nt++){
                const float* bp = &Bs[buf][(kk + tig)*BPAD + wn*64 + nt*8 + g];
                b[nt][0] = __float_as_uint(bp[0]);
                b[nt][1] = __float_as_uint(bp[4*BPAD]);
            }
            #pragma unroll
            for (int mt=0;mt<4;mt++)
                #pragma unroll
                for (int nt=0;nt<8;nt++)
                    mma_tf32(acc[mt][nt], a[mt], b[nt]);
        }
        __syncthreads();
    }

    bool isZ = (nb >= 512);
    #pragma unroll
    for (int mt=0;mt<4;mt++){
        int r0 = m0 + wm*64 + mt*16 + g;
        #pragma unroll
        for (int nt=0;nt<8;nt++){
            int n = nb + wn*64 + nt*8 + 2*tig;
            float b0v = g_bcat[n], b1v = g_bcat[n+1];
            float v00 = acc[mt][nt][0]+b0v, v01 = acc[mt][nt][1]+b1v;
            float v10 = acc[mt][nt][2]+b0v, v11 = acc[mt][nt][3]+b1v;
            if (isZ){
                int nz = n - 512;
                float2 lo = make_float2(tanh_a(v00), tanh_a(v01));
                float2 hi = make_float2(tanh_a(v10), tanh_a(v11));
                *(float2*)&g_z[(size_t)r0*HH + nz]     = lo;
                *(float2*)&g_z[(size_t)(r0+8)*HH + nz] = hi;
            } else {
                *(float2*)&g_xK[(size_t)r0*HH + n]     = make_float2(v00, v01);
                *(float2*)&g_xK[(size_t)(r0+8)*HH + n] = make_float2(v10, v11);
            }
        }
    }
}

// ---------------- 8) head ----------------
__global__ void __launch_bounds__(512) k_head(const float* __restrict__ bng, const float* __restrict__ bnb,
                                              const float* __restrict__ lng, const float* __restrict__ lnb,
                                              const float* __restrict__ Wc,  const float* __restrict__ bc,
                                              float* __restrict__ out){
    __shared__ float red[16];
    __shared__ float hsm[HH];
    __shared__ float lg[CC];
    int b = blockIdx.x, tid = threadIdx.x;

    float v = g_o[(b*TT + TT-1)*HH + tid];
    float y = (v - g_mean[tid])*g_rstd[tid]*bng[tid] + bnb[tid];

    float t1 = y;
    #pragma unroll
    for (int o=16;o;o>>=1) t1 += __shfl_xor_sync(~0u,t1,o);
    if ((tid&31)==0) red[tid>>5] = t1;
    __syncthreads();
    float mu = 0.f;
    #pragma unroll
    for (int i=0;i<16;i++) mu += red[i];
    mu *= (1.f/HH);
    __syncthreads();

    float d = y - mu;
    float t2 = d*d;
    #pragma unroll
    for (int o=16;o;o>>=1) t2 += __shfl_xor_sync(~0u,t2,o);
    if ((tid&31)==0) red[tid>>5] = t2;
    __syncthreads();
    float var = 0.f;
    #pragma unroll
    for (int i=0;i<16;i++) var += red[i];
    var *= (1.f/HH);
    float rs = rsqrtf(var + EPSF);
    hsm[tid] = d*rs*lng[tid] + lnb[tid];
    __syncthreads();

    int w = tid>>5, l = tid&31;
    if (w < CC){
        float p = 0.f;
        for (int k=l;k<HH;k+=32) p = fmaf(hsm[k], Wc[w*HH + k], p);
        #pragma unroll
        for (int o=16;o;o>>=1) p += __shfl_xor_sync(~0u,p,o);
        if (l==0) lg[w] = p + bc[w];
    }
    __syncthreads();
    if (tid==0){
        float mx = lg[0];
        #pragma unroll
        for (int c=1;c<CC;c++) mx = fmaxf(mx, lg[c]);
        float sm = 0.f;
        #pragma unroll
        for (int c=0;c<CC;c++) sm += expf(lg[c]-mx);
        float lse = mx + logf(sm);
        #pragma unroll
        for (int c=0;c<CC;c++) out[b*CC + c] = lg[c] - lse;
    }
}

// ---------------- launch sequence ----------------
extern "C" void kernel_launch(void* const* d_in, const int* in_sizes, int n_in,
                              void* d_out, int out_size){
    const float* x      = (const float*)d_in[0];
    const float* inln_g = (const float*)d_in[1];
    const float* inln_b = (const float*)d_in[2];
    const float* WxK1   = (const float*)d_in[3];
    const float* bxK1   = (const float*)d_in[4];
    const float* Wxz1   = (const float*)d_in[5];
    const float* bxz1   = (const float*)d_in[6];
    const float* WhK1   = (const float*)d_in[7];
    const float* bhK1   = (const float*)d_in[8];
    const float* bn1_g  = (const float*)d_in[9];
    const float* bn1_b  = (const float*)d_in[10];
    const float* WxK2   = (const float*)d_in[11];
    const float* bxK2   = (const float*)d_in[12];
    const float* Wxz2   = (const float*)d_in[13];
    const float* bxz2   = (const float*)d_in[14];
    const float* WhK2   = (const float*)d_in[15];
    const float* bhK2   = (const float*)d_in[16];
    const float* bn2_g  = (const float*)d_in[17];
    const float* bn2_b  = (const float*)d_in[18];
    const float* cln_g  = (const float*)d_in[19];
    const float* cln_b  = (const float*)d_in[20];
    const float* Wc     = (const float*)d_in[21];
    const float* bc     = (const float*)d_in[22];
    float* out = (float*)d_out;

    static int inited = 0;
    if (!inited){
        cudaFuncSetAttribute(k_pmma,  cudaFuncAttributeMaxDynamicSharedMemorySize, PMMA_SMEM);
        cudaFuncSetAttribute(k_recur, cudaFuncAttributeMaxDynamicSharedMemorySize, RSMEM2);
        inited = 1;
    }

    dim3 mg(BT/PM, 1024/PN);

    // input LN + layer-1 projections
    k_ln   <<<BT/256, 256>>>(x, inln_g, inln_b);
    k_proj1<<<BT/64, 512>>>(WxK1, bxK1, Wxz1, bxz1);

    // layer 1
    k_packW2  <<<256, 512>>>(WhK1);
    k_recur   <<<BB/8, 512, RSMEM2>>>(bhK1);
    k_statsfin<<<1, 512>>>(bn1_g, bn1_b);
    k_fold2   <<<HH, 256>>>(WxK2, bxK2, Wxz2, bxz2);

    // layer 2
    k_pmma    <<<mg, 256, PMMA_SMEM>>>();
    k_packW2  <<<256, 512>>>(WhK2);
    k_recur   <<<BB/8, 512, RSMEM2>>>(bhK2);
    k_statsfin<<<1, 512>>>(bn2_g, bn2_b);
    k_fold2   <<<HH, 256>>>(WxK2, bxK2, Wxz2, bxz2);

    // layer 3 (shared weights; g_W2hi/g_W2lo still hold packed WhK2)
    k_pmma    <<<mg, 256, PMMA_SMEM>>>();
    k_recur   <<<BB/8, 512, RSMEM2>>>(bhK2);
    k_statsfin<<<1, 512>>>(bn2_g, bn2_b);

    // head
    k_head <<<BB, 512>>>(bn2_g, bn2_b, cln_g, cln_b, Wc, bc, out);
}

// round 13
// speedup vs baseline: 1.0206x; 1.0206x over previous
#include <cuda_runtime.h>
#include <cuda_bf16.h>
#include <cstdint>

#define BB 1024
#define TT 128
#define DD 13
#define HH 512
#define CC 9
#define BT (BB*TT)
#define EPSF 1e-5f
#define NSLOT 64

#define PM 128
#define PN 256
#define PK 32
#define APAD 36
#define BPAD 260
#define PMMA_SMEM ((2*PM*APAD + 2*PK*BPAD)*4)

#define HP 260
#define RSMEM2 (4*16*HP*4)     // hi/lo x pingpong x 16 rows x HP = 66560 B

#define CLUSTER_SYNC() do{ \
    asm volatile("barrier.cluster.arrive.aligned;" ::: "memory"); \
    asm volatile("barrier.cluster.wait.aligned;"   ::: "memory"); \
}while(0)

// ---------------- scratch (device globals) ----------------
__device__ float g_xn[BT*16];
__device__ float g_xK[BT*HH];
__device__ float g_z [BT*HH];
__device__ float g_o [BT*HH];
__device__ float g_psum[NSLOT*HH];
__device__ float g_psq [NSLOT*HH];
__device__ float g_mean[HH], g_rstd[HH], g_s[HH], g_c[HH];
__device__ __align__(16) unsigned g_W2hi[256*512];   // fragment-major bf16 hi
__device__ __align__(16) unsigned g_W2lo[256*512];   // fragment-major bf16 lo residual
__device__ float g_Bt[512*1024];                     // tf32 BN-folded [Wk'|Wz'] as [k][n]
__device__ float g_bcat[1024];

// ---------------- helpers ----------------
__device__ __forceinline__ float tanh_a(float x){
    float r; asm("tanh.approx.f32 %0,%1;" : "=f"(r) : "f"(x)); return r;
}
__device__ __forceinline__ float sigm_a(float x){
    return fmaf(0.5f, tanh_a(0.5f*x), 0.5f);
}
__device__ __forceinline__ uint32_t cvt_tf32(float f){
    uint32_t u; asm("cvt.rna.tf32.f32 %0,%1;" : "=r"(u) : "f"(f)); return u;
}
__device__ __forceinline__ void cp16(uint32_t dst, const void* src){
    asm volatile("cp.async.ca.shared.global [%0],[%1],16;" :: "r"(dst), "l"(src));
}
__device__ __forceinline__ void mma_tf32(float* c, const uint32_t* a, const uint32_t* b){
    asm volatile("mma.sync.aligned.m16n8k8.row.col.f32.tf32.tf32.f32 "
        "{%0,%1,%2,%3},{%4,%5,%6,%7},{%8,%9},{%0,%1,%2,%3};"
        : "+f"(c[0]), "+f"(c[1]), "+f"(c[2]), "+f"(c[3])
        : "r"(a[0]), "r"(a[1]), "r"(a[2]), "r"(a[3]), "r"(b[0]), "r"(b[1]));
}
__device__ __forceinline__ void mma_bf16(float* c, const uint32_t* a, uint32_t b0, uint32_t b1){
    asm volatile("mma.sync.aligned.m16n8k16.row.col.f32.bf16.bf16.f32 "
        "{%0,%1,%2,%3},{%4,%5,%6,%7},{%8,%9},{%0,%1,%2,%3};"
        : "+f"(c[0]), "+f"(c[1]), "+f"(c[2]), "+f"(c[3])
        : "r"(a[0]), "r"(a[1]), "r"(a[2]), "r"(a[3]), "r"(b0), "r"(b1));
}

// ---------------- 1) input LayerNorm over D=13 ----------------
__global__ void k_ln(const float* __restrict__ x, const float* __restrict__ g,
                     const float* __restrict__ b){
    int m = blockIdx.x*blockDim.x + threadIdx.x;
    if (m >= BT) return;
    const float* r = x + m*DD;
    float s = 0.f;
    #pragma unroll
    for (int k=0;k<DD;k++) s += r[k];
    float mu = s * (1.f/DD);
    float v = 0.f;
    #pragma unroll
    for (int k=0;k<DD;k++){ float d = r[k]-mu; v += d*d; }
    float rs = rsqrtf(v*(1.f/DD) + EPSF);
    float* o = g_xn + m*16;
    #pragma unroll
    for (int k=0;k<DD;k++) o[k] = (r[k]-mu)*rs*g[k] + b[k];
    o[13]=0.f; o[14]=0.f; o[15]=0.f;
}

// ---------------- 2) layer-1 projections (K=13) ----------------
__global__ void __launch_bounds__(512) k_proj1(const float* __restrict__ WK, const float* __restrict__ bK,
                                               const float* __restrict__ WZ, const float* __restrict__ bZ){
    __shared__ float xt[64][16];
    int tid = threadIdx.x;
    int m0  = blockIdx.x*64;
    #pragma unroll
    for (int i=0;i<2;i++){
        int idx = tid + i*512;
        xt[idx>>4][idx&15] = g_xn[m0*16 + idx];
    }
    float wk[DD], wz[DD];
    #pragma unroll
    for (int i=0;i<DD;i++){ wk[i]=WK[tid*DD+i]; wz[i]=WZ[tid*DD+i]; }
    float bk = bK[tid], bz = bZ[tid];
    __syncthreads();
    for (int m=0;m<64;m++){
        float ak = bk, az = bz;
        #pragma unroll
        for (int i=0;i<DD;i++){ float xv = xt[m][i]; ak = fmaf(xv,wk[i],ak); az = fmaf(xv,wz[i],az); }
        g_xK[(m0+m)*HH + tid] = ak;
        g_z [(m0+m)*HH + tid] = tanh_a(az);
    }
}

// ---------------- 3) pack recurrence W: bf16 hi/lo, fragment-major ----------------
__global__ void k_packW2(const float* __restrict__ W){
    int kp = blockIdx.x;      // 0..255
    int j  = threadIdx.x;     // 0..511
    float2 wv = *(const float2*)&W[j*HH + 2*kp];
    __nv_bfloat16 h0 = __float2bfloat16(wv.x);
    __nv_bfloat16 h1 = __float2bfloat16(wv.y);
    __nv_bfloat16 l0 = __float2bfloat16(wv.x - __bfloat162float(h0));
    __nv_bfloat16 l1 = __float2bfloat16(wv.y - __bfloat162float(h1));
    int c = kp>>4, r = kp&15;
    int kt = r>>3, r2 = r&7;
    int p = r2>>2, tig = r2&3;
    int g = j&7, w = j>>5, nt = (j>>3)&3;
    int F = (((((c*2+kt)*2+p)*16 + w)*32 + g*4 + tig)<<2) + nt;
    __nv_bfloat162 ph; ph.x = h0; ph.y = h1;
    __nv_bfloat162 pl; pl.x = l0; pl.y = l1;
    g_W2hi[F] = *(unsigned*)&ph;
    g_W2lo[F] = *(unsigned*)&pl;
}

// ---------------- 4) recurrence: bf16x2-split MMA, 2-CTA cluster + fused BN stats ----------------
__global__ void __launch_bounds__(256,1) __cluster_dims__(2,1,1)
k_recur(const float* __restrict__ bh){
    extern __shared__ __align__(16) unsigned sm[];
    unsigned* Hb[2]; unsigned* Lb[2];
    Hb[0] = sm;            Hb[1] = sm + 16*HP;
    Lb[0] = sm + 32*HP;    Lb[1] = sm + 48*HP;

    const int tid  = threadIdx.x;
    const int wl   = tid >> 5;          // local warp 0..7
    const int lane = tid & 31;
    const int g    = lane >> 2;
    const int tig  = lane & 3;
    uint32_t rank; asm("mov.u32 %0,%%cluster_ctarank;" : "=r"(rank));
    const uint32_t peer = rank ^ 1u;
    const int w    = (int)rank*8 + wl;  // global warp id 0..15 (column group)
    const int b0r  = (blockIdx.x>>1)*16;

    for (int i=tid;i<16*HP;i+=256){ Hb[0][i]=0u; Lb[0][i]=0u; }

    float2 bhp[4];
    #pragma unroll
    for (int nt=0;nt<4;nt++) bhp[nt] = *(const float2*)&bh[w*32 + nt*8 + 2*tig];

    float2 ssA[4], sqA[4];
    #pragma unroll
    for (int nt=0;nt<4;nt++){ ssA[nt]=make_float2(0.f,0.f); sqA[nt]=make_float2(0.f,0.f); }

    const uint4* __restrict__ GH = (const uint4*)g_W2hi;
    const uint4* __restrict__ GL = (const uint4*)g_W2lo;
    const int off0 = w*32 + lane;

    __syncthreads();
    CLUSTER_SYNC();

    int p = 0;
    for (int t=0;t<TT;t++){
        // prefetch this step's gate inputs (independent of h)
        float2 gkp[4][2], zzp[4][2];
        long offs[4][2];
        #pragma unroll
        for (int nt=0;nt<4;nt++){
            int col = w*32 + nt*8 + 2*tig;
            #pragma unroll
            for (int rr=0;rr<2;rr++){
                int row = g + rr*8;
                long off = ((long)(b0r+row)*TT + t)*HH + col;
                offs[nt][rr] = off;
                gkp[nt][rr] = __ldcs((const float2*)(g_xK+off));
                zzp[nt][rr] = __ldcs((const float2*)(g_z +off));
            }
        }

        // dual accumulator banks per nt: break the 3-deep MMA RAW chain
        float accP[4][4], accQ[4][4];
        #pragma unroll
        for (int nt=0;nt<4;nt++){
            #pragma unroll
            for (int i=0;i<4;i++){ accP[nt][i]=0.f; accQ[nt][i]=0.f; }
        }

        const unsigned* hp = Hb[p];
        const unsigned* lp = Lb[p];

        // prefetch stages 0,1 of W fragments
        uint4 f[2][4];
        #pragma unroll
        for (int s=0;s<2;s++){
            f[s][0] = __ldg(GH + s*1024 + off0);
            f[s][1] = __ldg(GH + s*1024 + 512 + off0);
            f[s][2] = __ldg(GL + s*1024 + off0);
            f[s][3] = __ldg(GL + s*1024 + 512 + off0);
        }

        #pragma unroll 2
        for (int i=0;i<32;i++){
            int s = i & 1;
            uint4 bh0 = f[s][0], bh1 = f[s][1], bl0 = f[s][2], bl1 = f[s][3];
            if (i < 30){
                int ni = i + 2;
                f[s][0] = __ldg(GH + ni*1024 + off0);
                f[s][1] = __ldg(GH + ni*1024 + 512 + off0);
                f[s][2] = __ldg(GL + ni*1024 + off0);
                f[s][3] = __ldg(GL + ni*1024 + 512 + off0);
            }
            int kpg = i*8;
            uint32_t ah[4], al[4];
            ah[0] = hp[ g   *HP + kpg + tig];
            ah[1] = hp[(g+8)*HP + kpg + tig];
            ah[2] = hp[ g   *HP + kpg + tig + 4];
            ah[3] = hp[(g+8)*HP + kpg + tig + 4];
            al[0] = lp[ g   *HP + kpg + tig];
            al[1] = lp[(g+8)*HP + kpg + tig];
            al[2] = lp[ g   *HP + kpg + tig + 4];
            al[3] = lp[(g+8)*HP + kpg + tig + 4];

            const uint32_t* b0h = (const uint32_t*)&bh0;
            const uint32_t* b1h = (const uint32_t*)&bh1;
            const uint32_t* b0l = (const uint32_t*)&bl0;
            const uint32_t* b1l = (const uint32_t*)&bl1;
            #pragma unroll
            for (int nt=0;nt<4;nt++){
                mma_bf16(accP[nt], ah, b0h[nt], b1h[nt]);   // main product -> bank P
                mma_bf16(accQ[nt], ah, b0l[nt], b1l[nt]);   // residuals   -> bank Q
                mma_bf16(accQ[nt], al, b0h[nt], b1h[nt]);
            }
        }

        // epilogue: gates + h update + local & remote (DSMEM) h store + stats
        unsigned* Hn = Hb[1-p];
        unsigned* Ln = Lb[1-p];
        uint32_t lHn = (uint32_t)__cvta_generic_to_shared(Hn);
        uint32_t lLn = (uint32_t)__cvta_generic_to_shared(Ln);
        uint32_t rHn, rLn;
        asm("mapa.shared::cluster.u32 %0,%1,%2;" : "=r"(rHn) : "r"(lHn), "r"(peer));
        asm("mapa.shared::cluster.u32 %0,%1,%2;" : "=r"(rLn) : "r"(lLn), "r"(peer));

        #pragma unroll
        for (int nt=0;nt<4;nt++){
            int col = w*32 + nt*8 + 2*tig;
            int kp  = col >> 1;
            #pragma unroll
            for (int rr=0;rr<2;rr++){
                int row = g + rr*8;
                long off = offs[nt][rr];
                float2 gk = gkp[nt][rr];
                float2 zz = zzp[nt][rr];
                unsigned uh = hp[row*HP+kp], ul = lp[row*HP+kp];
                __nv_bfloat162 bh2 = *(__nv_bfloat162*)&uh;
                __nv_bfloat162 bl2 = *(__nv_bfloat162*)&ul;
                float ho0 = __bfloat162float(bh2.x) + __bfloat162float(bl2.x);
                float ho1 = __bfloat162float(bh2.y) + __bfloat162float(bl2.y);
                float a0 = accP[nt][rr*2+0] + accQ[nt][rr*2+0];
                float a1 = accP[nt][rr*2+1] + accQ[nt][rr*2+1];
                float K0 = sigm_a(gk.x + a0 + bhp[nt].x);
                float K1 = sigm_a(gk.y + a1 + bhp[nt].y);
                float hn0 = tanh_a(fmaf(K0, ho0 - zz.x, zz.x));
                float hn1 = tanh_a(fmaf(K1, ho1 - zz.y, zz.y));
                // tf32-rounded output (pmma A consumes tf32 anyway)
                float r0 = __uint_as_float(cvt_tf32(hn0));
                float r1 = __uint_as_float(cvt_tf32(hn1));
                __stcs((float2*)(g_o+off), make_float2(r0, r1));
                ssA[nt].x += r0;  ssA[nt].y += r1;
                sqA[nt].x = fmaf(r0, r0, sqA[nt].x);
                sqA[nt].y = fmaf(r1, r1, sqA[nt].y);
                // bf16 hi/lo repack
                __nv_bfloat162 ph2 = __floats2bfloat162_rn(hn0, hn1);
                float2 hf = __bfloat1622float2(ph2);
                __nv_bfloat162 pl2 = __floats2bfloat162_rn(hn0 - hf.x, hn1 - hf.y);
                unsigned vh = *(unsigned*)&ph2;
                unsigned vl = *(unsigned*)&pl2;
                int idx = row*HP + kp;
                Hn[idx] = vh;
                Ln[idx] = vl;
                asm volatile("st.shared::cluster.u32 [%0], %1;" :: "r"(rHn + (uint32_t)idx*4u), "r"(vh));
                asm volatile("st.shared::cluster.u32 [%0], %1;" :: "r"(rLn + (uint32_t)idx*4u), "r"(vl));
            }
        }
        CLUSTER_SYNC();
        p ^= 1;
    }

    // reduce stats over the 8 row-lanes (g = lane bits 2..4), write per-cluster partials
    #pragma unroll
    for (int nt=0;nt<4;nt++){
        #pragma unroll
        for (int o=4;o<=16;o<<=1){
            ssA[nt].x += __shfl_xor_sync(~0u, ssA[nt].x, o);
            ssA[nt].y += __shfl_xor_sync(~0u, ssA[nt].y, o);
            sqA[nt].x += __shfl_xor_sync(~0u, sqA[nt].x, o);
            sqA[nt].y += __shfl_xor_sync(~0u, sqA[nt].y, o);
        }
    }
    if (lane < 4){
        int slot = blockIdx.x >> 1;
        #pragma unroll
        for (int nt=0;nt<4;nt++){
            int col = w*32 + nt*8 + 2*lane;
            g_psum[slot*HH + col]     = ssA[nt].x;
            g_psum[slot*HH + col + 1] = ssA[nt].y;
            g_psq [slot*HH + col]     = sqA[nt].x;
            g_psq [slot*HH + col + 1] = sqA[nt].y;
        }
    }
}

// ---------------- 5) finalize BN stats + fold vectors ----------------
__global__ void k_statsfin(const float* __restrict__ bng, const float* __restrict__ bnb){
    int t = threadIdx.x;
    float s = 0.f, q = 0.f;
    for (int i=0;i<NSLOT;i++){ s += g_psum[i*HH + t]; q += g_psq[i*HH + t]; }
    float m  = s * (1.f/BT);
    float v  = q * (1.f/BT) - m*m;
    float rs = rsqrtf(v + EPSF);
    g_mean[t] = m;
    g_rstd[t] = rs;
    float sc = bng[t]*rs;
    g_s[t] = sc;
    g_c[t] = bnb[t] - m*sc;
}

// ---------------- 6) fold: biases + tf32 B pack ----------------
__global__ void k_fold2(const float* __restrict__ WK, const float* __restrict__ bK,
                        const float* __restrict__ WZ, const float* __restrict__ bZ){
    __shared__ float sk[8], sz[8];
    int j = blockIdx.x, t = threadIdx.x;
    float ck = 0.f, cz = 0.f;
    for (int k=t;k<HH;k+=256){
        float wkv = WK[j*HH+k];
        float wzv = WZ[j*HH+k];
        float c = g_c[k];
        float sv = g_s[k];
        ck = fmaf(wkv, c, ck);
        cz = fmaf(wzv, c, cz);
        g_Bt[k*1024 + j]       = __uint_as_float(cvt_tf32(wkv*sv));
        g_Bt[k*1024 + 512 + j] = __uint_as_float(cvt_tf32(wzv*sv));
    }
    #pragma unroll
    for (int o=16;o;o>>=1){ ck += __shfl_xor_sync(~0u,ck,o); cz += __shfl_xor_sync(~0u,cz,o); }
    if ((t&31)==0){ sk[t>>5]=ck; sz[t>>5]=cz; }
    __syncthreads();
    if (t==0){
        float a=0.f,b2=0.f;
        #pragma unroll
        for (int i=0;i<8;i++){ a+=sk[i]; b2+=sz[i]; }
        g_bcat[j]     = bK[j] + a;
        g_bcat[512+j] = bZ[j] + b2;
    }
}

// ---------------- 7) layer-2/3 projections: tf32 tensor GEMM (A pre-rounded) ----------------
__global__ void __launch_bounds__(256,1) k_pmma(){
    extern __shared__ float smem[];
    float* As[2] = { smem, smem + PM*APAD };
    float* Bs[2] = { smem + 2*PM*APAD, smem + 2*PM*APAD + PK*BPAD };
    uint32_t sA[2], sB[2];
    sA[0] = (uint32_t)__cvta_generic_to_shared(As[0]);
    sA[1] = (uint32_t)__cvta_generic_to_shared(As[1]);
    sB[0] = (uint32_t)__cvta_generic_to_shared(Bs[0]);
    sB[1] = (uint32_t)__cvta_generic_to_shared(Bs[1]);

    int tid = threadIdx.x;
    int wid = tid>>5, lane = tid&31;
    int g = lane>>2, tig = lane&3;
    int wm = wid & 1, wn = wid >> 1;
    int m0 = blockIdx.x * PM;
    int nb = blockIdx.y * PN;

    const float* Ag = g_o  + (size_t)m0*HH;
    const float* Bg = g_Bt + nb;

    float acc[4][8][4];
    #pragma unroll
    for (int mt=0;mt<4;mt++)
        #pragma unroll
        for (int nt=0;nt<8;nt++)
            #pragma unroll
            for (int i=0;i<4;i++) acc[mt][nt][i]=0.f;

    auto stage = [&](int c, int buf){
        #pragma unroll
        for (int i=0;i<4;i++){
            int u = i*256 + tid;
            int row = u>>3, seg = u&7;
            cp16(sA[buf] + (row*APAD + seg*4)*4, Ag + row*HH + c*PK + seg*4);
        }
        #pragma unroll
        for (int i=0;i<8;i++){
            int u = i*256 + tid;
            int row = u>>6, seg = u&63;
            cp16(sB[buf] + (row*BPAD + seg*4)*4, Bg + (size_t)(c*PK + row)*1024 + seg*4);
        }
        asm volatile("cp.async.commit_group;");
    };

    stage(0, 0);
    #pragma unroll 1
    for (int c=0;c<16;c++){
        int buf = c & 1;
        if (c < 15) stage(c+1, buf^1);
        if (c < 15) asm volatile("cp.async.wait_group 1;");
        else        asm volatile("cp.async.wait_group 0;");
        __syncthreads();

        #pragma unroll
        for (int k8=0;k8<4;k8++){
            int kk = k8*8;
            uint32_t a[4][4];
            #pragma unroll
            for (int mt=0;mt<4;mt++){
                const float* ap = &As[buf][(wm*64 + mt*16 + g)*APAD + kk + tig];
                a[mt][0] = __float_as_uint(ap[0]);
                a[mt][1] = __float_as_uint(ap[8*APAD]);
                a[mt][2] = __float_as_uint(ap[4]);
                a[mt][3] = __float_as_uint(ap[8*APAD+4]);
            }
            uint32_t b[8][2];
            #pragma unroll
            for (int nt=0;nt<8;nt++){
                const float* bp = &Bs[buf][(kk + tig)*BPAD + wn*64 + nt*8 + g];
                b[nt][0] = __float_as_uint(bp[0]);
                b[nt][1] = __float_as_uint(bp[4*BPAD]);
            }
            #pragma unroll
            for (int mt=0;mt<4;mt++)
                #pragma unroll
                for (int nt=0;nt<8;nt++)
                    mma_tf32(acc[mt][nt], a[mt], b[nt]);
        }
        __syncthreads();
    }

    bool isZ = (nb >= 512);
    #pragma unroll
    for (int mt=0;mt<4;mt++){
        int r0 = m0 + wm*64 + mt*16 + g;
        #pragma unroll
        for (int nt=0;nt<8;nt++){
            int n = nb + wn*64 + nt*8 + 2*tig;
            float b0v = g_bcat[n], b1v = g_bcat[n+1];
            float v00 = acc[mt][nt][0]+b0v, v01 = acc[mt][nt][1]+b1v;
            float v10 = acc[mt][nt][2]+b0v, v11 = acc[mt][nt][3]+b1v;
            if (isZ){
                int nz = n - 512;
                float2 lo = make_float2(tanh_a(v00), tanh_a(v01));
                float2 hi = make_float2(tanh_a(v10), tanh_a(v11));
                *(float2*)&g_z[(size_t)r0*HH + nz]     = lo;
                *(float2*)&g_z[(size_t)(r0+8)*HH + nz] = hi;
            } else {
                *(float2*)&g_xK[(size_t)r0*HH + n]     = make_float2(v00, v01);
                *(float2*)&g_xK[(size_t)(r0+8)*HH + n] = make_float2(v10, v11);
            }
        }
    }
}

// ---------------- 8) head ----------------
__global__ void __launch_bounds__(512) k_head(const float* __restrict__ bng, const float* __restrict__ bnb,
                                              const float* __restrict__ lng, const float* __restrict__ lnb,
                                              const float* __restrict__ Wc,  const float* __restrict__ bc,
                                              float* __restrict__ out){
    __shared__ float red[16];
    __shared__ float hsm[HH];
    __shared__ float lg[CC];
    int b = blockIdx.x, tid = threadIdx.x;

    float v = g_o[(b*TT + TT-1)*HH + tid];
    float y = (v - g_mean[tid])*g_rstd[tid]*bng[tid] + bnb[tid];

    float t1 = y;
    #pragma unroll
    for (int o=16;o;o>>=1) t1 += __shfl_xor_sync(~0u,t1,o);
    if ((tid&31)==0) red[tid>>5] = t1;
    __syncthreads();
    float mu = 0.f;
    #pragma unroll
    for (int i=0;i<16;i++) mu += red[i];
    mu *= (1.f/HH);
    __syncthreads();

    float d = y - mu;
    float t2 = d*d;
    #pragma unroll
    for (int o=16;o;o>>=1) t2 += __shfl_xor_sync(~0u,t2,o);
    if ((tid&31)==0) red[tid>>5] = t2;
    __syncthreads();
    float var = 0.f;
    #pragma unroll
    for (int i=0;i<16;i++) var += red[i];
    var *= (1.f/HH);
    float rs = rsqrtf(var + EPSF);
    hsm[tid] = d*rs*lng[tid] + lnb[tid];
    __syncthreads();

    int w = tid>>5, l = tid&31;
    if (w < CC){
        float p = 0.f;
        for (int k=l;k<HH;k+=32) p = fmaf(hsm[k], Wc[w*HH + k], p);
        #pragma unroll
        for (int o=16;o;o>>=1) p += __shfl_xor_sync(~0u,p,o);
        if (l==0) lg[w] = p + bc[w];
    }
    __syncthreads();
    if (tid==0){
        float mx = lg[0];
        #pragma unroll
        for (int c=1;c<CC;c++) mx = fmaxf(mx, lg[c]);
        float sm = 0.f;
        #pragma unroll
        for (int c=0;c<CC;c++) sm += expf(lg[c]-mx);
        float lse = mx + logf(sm);
        #pragma unroll
        for (int c=0;c<CC;c++) out[b*CC + c] = lg[c] - lse;
    }
}

// ---------------- launch sequence ----------------
extern "C" void kernel_launch(void* const* d_in, const int* in_sizes, int n_in,
                              void* d_out, int out_size){
    const float* x      = (const float*)d_in[0];
    const float* inln_g = (const float*)d_in[1];
    const float* inln_b = (const float*)d_in[2];
    const float* WxK1   = (const float*)d_in[3];
    const float* bxK1   = (const float*)d_in[4];
    const float* Wxz1   = (const float*)d_in[5];
    const float* bxz1   = (const float*)d_in[6];
    const float* WhK1   = (const float*)d_in[7];
    const float* bhK1   = (const float*)d_in[8];
    const float* bn1_g  = (const float*)d_in[9];
    const float* bn1_b  = (const float*)d_in[10];
    const float* WxK2   = (const float*)d_in[11];
    const float* bxK2   = (const float*)d_in[12];
    const float* Wxz2   = (const float*)d_in[13];
    const float* bxz2   = (const float*)d_in[14];
    const float* WhK2   = (const float*)d_in[15];
    const float* bhK2   = (const float*)d_in[16];
    const float* bn2_g  = (const float*)d_in[17];
    const float* bn2_b  = (const float*)d_in[18];
    const float* cln_g  = (const float*)d_in[19];
    const float* cln_b  = (const float*)d_in[20];
    const float* Wc     = (const float*)d_in[21];
    const float* bc     = (const float*)d_in[22];
    float* out = (float*)d_out;

    static int inited = 0;
    if (!inited){
        cudaFuncSetAttribute(k_pmma,  cudaFuncAttributeMaxDynamicSharedMemorySize, PMMA_SMEM);
        cudaFuncSetAttribute(k_recur, cudaFuncAttributeMaxDynamicSharedMemorySize, RSMEM2);
        inited = 1;
    }

    dim3 mg(BT/PM, 1024/PN);

    // input LN + layer-1 projections
    k_ln   <<<BT/256, 256>>>(x, inln_g, inln_b);
    k_proj1<<<BT/64, 512>>>(WxK1, bxK1, Wxz1, bxz1);

    // layer 1
    k_packW2  <<<256, 512>>>(WhK1);
    k_recur   <<<BB/8, 256, RSMEM2>>>(bhK1);
    k_statsfin<<<1, 512>>>(bn1_g, bn1_b);
    k_fold2   <<<HH, 256>>>(WxK2, bxK2, Wxz2, bxz2);

    // layer 2
    k_pmma    <<<mg, 256, PMMA_SMEM>>>();
    k_packW2  <<<256, 512>>>(WhK2);
    k_recur   <<<BB/8, 256, RSMEM2>>>(bhK2);
    k_statsfin<<<1, 512>>>(bn2_g, bn2_b);
    k_fold2   <<<HH, 256>>>(WxK2, bxK2, Wxz2, bxz2);

    // layer 3 (shared weights; g_W2hi/g_W2lo still hold packed WhK2)
    k_pmma    <<<mg, 256, PMMA_SMEM>>>();
    k_recur   <<<BB/8, 256, RSMEM2>>>(bhK2);
    k_statsfin<<<1, 512>>>(bn2_g, bn2_b);

    // head
    k_head <<<BB, 512>>>(bn2_g, bn2_b, cln_g, cln_b, Wc, bc, out);
}

// round 16
// speedup vs baseline: 1.0742x; 1.0524x over previous
#include <cuda_runtime.h>
#include <cuda_bf16.h>
#include <cstdint>

#define BB 1024
#define TT 128
#define DD 13
#define HH 512
#define CC 9
#define BT (BB*TT)
#define EPSF 1e-5f
#define NSLOT 64

#define PM 128
#define PN 128
#define PK 32
#define APAD 36
#define BPAD 132
#define PMMA_SMEM ((2*PM*APAD + 2*PK*BPAD)*4)

#define HP 260
#define RSMEM2 (4*16*HP*4)     // hi/lo x pingpong x 16 rows x HP = 66560 B

#define CLUSTER_SYNC() do{ \
    asm volatile("barrier.cluster.arrive.aligned;" ::: "memory"); \
    asm volatile("barrier.cluster.wait.aligned;"   ::: "memory"); \
}while(0)

// ---------------- scratch (device globals) ----------------
__device__ float g_xn[BT*16];
__device__ float g_xK[BT*HH];
__device__ float g_z [BT*HH];
__device__ float g_o [BT*HH];
__device__ float g_psum[NSLOT*HH];
__device__ float g_psq [NSLOT*HH];
__device__ float g_mean[HH], g_rstd[HH], g_s[HH], g_c[HH];
__device__ __align__(16) unsigned g_W2hi[256*512];   // fragment-major bf16 hi
__device__ __align__(16) unsigned g_W2lo[256*512];   // fragment-major bf16 lo residual
__device__ float g_Bt[512*1024];                     // tf32 BN-folded [Wk'|Wz'] as [k][n]
__device__ float g_bcat[1024];

// ---------------- helpers ----------------
__device__ __forceinline__ float tanh_a(float x){
    float r; asm("tanh.approx.f32 %0,%1;" : "=f"(r) : "f"(x)); return r;
}
__device__ __forceinline__ float sigm_a(float x){
    return fmaf(0.5f, tanh_a(0.5f*x), 0.5f);
}
__device__ __forceinline__ uint32_t cvt_tf32(float f){
    uint32_t u; asm("cvt.rna.tf32.f32 %0,%1;" : "=r"(u) : "f"(f)); return u;
}
__device__ __forceinline__ void cp16(uint32_t dst, const void* src){
    asm volatile("cp.async.ca.shared.global [%0],[%1],16;" :: "r"(dst), "l"(src));
}
__device__ __forceinline__ void mma_tf32(float* c, const uint32_t* a, const uint32_t* b){
    asm volatile("mma.sync.aligned.m16n8k8.row.col.f32.tf32.tf32.f32 "
        "{%0,%1,%2,%3},{%4,%5,%6,%7},{%8,%9},{%0,%1,%2,%3};"
        : "+f"(c[0]), "+f"(c[1]), "+f"(c[2]), "+f"(c[3])
        : "r"(a[0]), "r"(a[1]), "r"(a[2]), "r"(a[3]), "r"(b[0]), "r"(b[1]));
}
__device__ __forceinline__ void mma_bf16(float* c, const uint32_t* a, uint32_t b0, uint32_t b1){
    asm volatile("mma.sync.aligned.m16n8k16.row.col.f32.bf16.bf16.f32 "
        "{%0,%1,%2,%3},{%4,%5,%6,%7},{%8,%9},{%0,%1,%2,%3};"
        : "+f"(c[0]), "+f"(c[1]), "+f"(c[2]), "+f"(c[3])
        : "r"(a[0]), "r"(a[1]), "r"(a[2]), "r"(a[3]), "r"(b0), "r"(b1));
}

// ---------------- 1) input LayerNorm over D=13 ----------------
__global__ void k_ln(const float* __restrict__ x, const float* __restrict__ g,
                     const float* __restrict__ b){
    int m = blockIdx.x*blockDim.x + threadIdx.x;
    if (m >= BT) return;
    const float* r = x + m*DD;
    float s = 0.f;
    #pragma unroll
    for (int k=0;k<DD;k++) s += r[k];
    float mu = s * (1.f/DD);
    float v = 0.f;
    #pragma unroll
    for (int k=0;k<DD;k++){ float d = r[k]-mu; v += d*d; }
    float rs = rsqrtf(v*(1.f/DD) + EPSF);
    float* o = g_xn + m*16;
    #pragma unroll
    for (int k=0;k<DD;k++) o[k] = (r[k]-mu)*rs*g[k] + b[k];
    o[13]=0.f; o[14]=0.f; o[15]=0.f;
}

// ---------------- 2) layer-1 projections (K=13) ----------------
__global__ void __launch_bounds__(512) k_proj1(const float* __restrict__ WK, const float* __restrict__ bK,
                                               const float* __restrict__ WZ, const float* __restrict__ bZ){
    __shared__ float xt[64][16];
    int tid = threadIdx.x;
    int m0  = blockIdx.x*64;
    #pragma unroll
    for (int i=0;i<2;i++){
        int idx = tid + i*512;
        xt[idx>>4][idx&15] = g_xn[m0*16 + idx];
    }
    float wk[DD], wz[DD];
    #pragma unroll
    for (int i=0;i<DD;i++){ wk[i]=WK[tid*DD+i]; wz[i]=WZ[tid*DD+i]; }
    float bk = bK[tid], bz = bZ[tid];
    __syncthreads();
    for (int m=0;m<64;m++){
        float ak = bk, az = bz;
        #pragma unroll
        for (int i=0;i<DD;i++){ float xv = xt[m][i]; ak = fmaf(xv,wk[i],ak); az = fmaf(xv,wz[i],az); }
        g_xK[(m0+m)*HH + tid] = ak;
        g_z [(m0+m)*HH + tid] = tanh_a(az);
    }
}

// ---------------- 3) pack recurrence W: bf16 hi/lo, fragment-major ----------------
__global__ void k_packW2(const float* __restrict__ W){
    int kp = blockIdx.x;      // 0..255
    int j  = threadIdx.x;     // 0..511
    float2 wv = *(const float2*)&W[j*HH + 2*kp];
    __nv_bfloat16 h0 = __float2bfloat16(wv.x);
    __nv_bfloat16 h1 = __float2bfloat16(wv.y);
    __nv_bfloat16 l0 = __float2bfloat16(wv.x - __bfloat162float(h0));
    __nv_bfloat16 l1 = __float2bfloat16(wv.y - __bfloat162float(h1));
    int c = kp>>4, r = kp&15;
    int kt = r>>3, r2 = r&7;
    int p = r2>>2, tig = r2&3;
    int g = j&7, w = j>>5, nt = (j>>3)&3;
    int F = (((((c*2+kt)*2+p)*16 + w)*32 + g*4 + tig)<<2) + nt;
    __nv_bfloat162 ph; ph.x = h0; ph.y = h1;
    __nv_bfloat162 pl; pl.x = l0; pl.y = l1;
    g_W2hi[F] = *(unsigned*)&ph;
    g_W2lo[F] = *(unsigned*)&pl;
}

// ---------------- 4) recurrence: R11 — bf16x2-split MMA, 2-CTA cluster + fused stats ----------------
__global__ void __launch_bounds__(256,1) __cluster_dims__(2,1,1)
k_recur(const float* __restrict__ bh){
    extern __shared__ __align__(16) unsigned sm[];
    unsigned* Hb[2]; unsigned* Lb[2];
    Hb[0] = sm;            Hb[1] = sm + 16*HP;
    Lb[0] = sm + 32*HP;    Lb[1] = sm + 48*HP;

    const int tid  = threadIdx.x;
    const int wl   = tid >> 5;          // local warp 0..7
    const int lane = tid & 31;
    const int g    = lane >> 2;
    const int tig  = lane & 3;
    uint32_t rank; asm("mov.u32 %0,%%cluster_ctarank;" : "=r"(rank));
    const uint32_t peer = rank ^ 1u;
    const int w    = (int)rank*8 + wl;  // global warp id 0..15 (column group)
    const int b0r  = (blockIdx.x>>1)*16;

    for (int i=tid;i<16*HP;i+=256){ Hb[0][i]=0u; Lb[0][i]=0u; }

    float2 bhp[4];
    #pragma unroll
    for (int nt=0;nt<4;nt++) bhp[nt] = *(const float2*)&bh[w*32 + nt*8 + 2*tig];

    float2 ssA[4], sqA[4];
    #pragma unroll
    for (int nt=0;nt<4;nt++){ ssA[nt]=make_float2(0.f,0.f); sqA[nt]=make_float2(0.f,0.f); }

    const uint4* __restrict__ GH = (const uint4*)g_W2hi;
    const uint4* __restrict__ GL = (const uint4*)g_W2lo;
    const int off0 = w*32 + lane;

    __syncthreads();
    CLUSTER_SYNC();

    int p = 0;
    for (int t=0;t<TT;t++){
        float2 gkp[4][2], zzp[4][2];
        long offs[4][2];
        #pragma unroll
        for (int nt=0;nt<4;nt++){
            int col = w*32 + nt*8 + 2*tig;
            #pragma unroll
            for (int rr=0;rr<2;rr++){
                int row = g + rr*8;
                long off = ((long)(b0r+row)*TT + t)*HH + col;
                offs[nt][rr] = off;
                gkp[nt][rr] = __ldcs((const float2*)(g_xK+off));
                zzp[nt][rr] = __ldcs((const float2*)(g_z +off));
            }
        }

        float acc[4][4];
        #pragma unroll
        for (int nt=0;nt<4;nt++){ acc[nt][0]=0.f; acc[nt][1]=0.f; acc[nt][2]=0.f; acc[nt][3]=0.f; }

        const unsigned* hp = Hb[p];
        const unsigned* lp = Lb[p];

        uint4 f[2][4];
        #pragma unroll
        for (int s=0;s<2;s++){
            f[s][0] = __ldg(GH + s*1024 + off0);
            f[s][1] = __ldg(GH + s*1024 + 512 + off0);
            f[s][2] = __ldg(GL + s*1024 + off0);
            f[s][3] = __ldg(GL + s*1024 + 512 + off0);
        }

        #pragma unroll 2
        for (int i=0;i<32;i++){
            int s = i & 1;
            uint4 bh0 = f[s][0], bh1 = f[s][1], bl0 = f[s][2], bl1 = f[s][3];
            if (i < 30){
                int ni = i + 2;
                f[s][0] = __ldg(GH + ni*1024 + off0);
                f[s][1] = __ldg(GH + ni*1024 + 512 + off0);
                f[s][2] = __ldg(GL + ni*1024 + off0);
                f[s][3] = __ldg(GL + ni*1024 + 512 + off0);
            }
            int kpg = i*8;
            uint32_t ah[4], al[4];
            ah[0] = hp[ g   *HP + kpg + tig];
            ah[1] = hp[(g+8)*HP + kpg + tig];
            ah[2] = hp[ g   *HP + kpg + tig + 4];
            ah[3] = hp[(g+8)*HP + kpg + tig + 4];
            al[0] = lp[ g   *HP + kpg + tig];
            al[1] = lp[(g+8)*HP + kpg + tig];
            al[2] = lp[ g   *HP + kpg + tig + 4];
            al[3] = lp[(g+8)*HP + kpg + tig + 4];

            const uint32_t* b0h = (const uint32_t*)&bh0;
            const uint32_t* b1h = (const uint32_t*)&bh1;
            const uint32_t* b0l = (const uint32_t*)&bl0;
            const uint32_t* b1l = (const uint32_t*)&bl1;
            #pragma unroll
            for (int nt=0;nt<4;nt++){
                mma_bf16(acc[nt], ah, b0h[nt], b1h[nt]);
                mma_bf16(acc[nt], ah, b0l[nt], b1l[nt]);
                mma_bf16(acc[nt], al, b0h[nt], b1h[nt]);
            }
        }

        unsigned* Hn = Hb[1-p];
        unsigned* Ln = Lb[1-p];
        uint32_t lHn = (uint32_t)__cvta_generic_to_shared(Hn);
        uint32_t lLn = (uint32_t)__cvta_generic_to_shared(Ln);
        uint32_t rHn, rLn;
        asm("mapa.shared::cluster.u32 %0,%1,%2;" : "=r"(rHn) : "r"(lHn), "r"(peer));
        asm("mapa.shared::cluster.u32 %0,%1,%2;" : "=r"(rLn) : "r"(lLn), "r"(peer));

        #pragma unroll
        for (int nt=0;nt<4;nt++){
            int col = w*32 + nt*8 + 2*tig;
            int kp  = col >> 1;
            #pragma unroll
            for (int rr=0;rr<2;rr++){
                int row = g + rr*8;
                long off = offs[nt][rr];
                float2 gk = gkp[nt][rr];
                float2 zz = zzp[nt][rr];
                unsigned uh = hp[row*HP+kp], ul = lp[row*HP+kp];
                __nv_bfloat162 bh2 = *(__nv_bfloat162*)&uh;
                __nv_bfloat162 bl2 = *(__nv_bfloat162*)&ul;
                float ho0 = __bfloat162float(bh2.x) + __bfloat162float(bl2.x);
                float ho1 = __bfloat162float(bh2.y) + __bfloat162float(bl2.y);
                float K0 = sigm_a(gk.x + acc[nt][rr*2+0] + bhp[nt].x);
                float K1 = sigm_a(gk.y + acc[nt][rr*2+1] + bhp[nt].y);
                float hn0 = tanh_a(fmaf(K0, ho0 - zz.x, zz.x));
                float hn1 = tanh_a(fmaf(K1, ho1 - zz.y, zz.y));
                float r0 = __uint_as_float(cvt_tf32(hn0));
                float r1 = __uint_as_float(cvt_tf32(hn1));
                __stcs((float2*)(g_o+off), make_float2(r0, r1));
                ssA[nt].x += r0;  ssA[nt].y += r1;
                sqA[nt].x = fmaf(r0, r0, sqA[nt].x);
                sqA[nt].y = fmaf(r1, r1, sqA[nt].y);
                __nv_bfloat162 ph2 = __floats2bfloat162_rn(hn0, hn1);
                float2 hf = __bfloat1622float2(ph2);
                __nv_bfloat162 pl2 = __floats2bfloat162_rn(hn0 - hf.x, hn1 - hf.y);
                unsigned vh = *(unsigned*)&ph2;
                unsigned vl = *(unsigned*)&pl2;
                int idx = row*HP + kp;
                Hn[idx] = vh;
                Ln[idx] = vl;
                asm volatile("st.shared::cluster.u32 [%0], %1;" :: "r"(rHn + (uint32_t)idx*4u), "r"(vh));
                asm volatile("st.shared::cluster.u32 [%0], %1;" :: "r"(rLn + (uint32_t)idx*4u), "r"(vl));
            }
        }
        CLUSTER_SYNC();
        p ^= 1;
    }

    #pragma unroll
    for (int nt=0;nt<4;nt++){
        #pragma unroll
        for (int o=4;o<=16;o<<=1){
            ssA[nt].x += __shfl_xor_sync(~0u, ssA[nt].x, o);
            ssA[nt].y += __shfl_xor_sync(~0u, ssA[nt].y, o);
            sqA[nt].x += __shfl_xor_sync(~0u, sqA[nt].x, o);
            sqA[nt].y += __shfl_xor_sync(~0u, sqA[nt].y, o);
        }
    }
    if (lane < 4){
        int slot = blockIdx.x >> 1;
        #pragma unroll
        for (int nt=0;nt<4;nt++){
            int col = w*32 + nt*8 + 2*lane;
            g_psum[slot*HH + col]     = ssA[nt].x;
            g_psum[slot*HH + col + 1] = ssA[nt].y;
            g_psq [slot*HH + col]     = sqA[nt].x;
            g_psq [slot*HH + col + 1] = sqA[nt].y;
        }
    }
}

// ---------------- 5) finalize BN stats + fold vectors ----------------
__global__ void k_statsfin(const float* __restrict__ bng, const float* __restrict__ bnb){
    int t = threadIdx.x;
    float s = 0.f, q = 0.f;
    for (int i=0;i<NSLOT;i++){ s += g_psum[i*HH + t]; q += g_psq[i*HH + t]; }
    float m  = s * (1.f/BT);
    float v  = q * (1.f/BT) - m*m;
    float rs = rsqrtf(v + EPSF);
    g_mean[t] = m;
    g_rstd[t] = rs;
    float sc = bng[t]*rs;
    g_s[t] = sc;
    g_c[t] = bnb[t] - m*sc;
}

// ---------------- 6) fold: biases + tf32 B pack ----------------
__global__ void k_fold2(const float* __restrict__ WK, const float* __restrict__ bK,
                        const float* __restrict__ WZ, const float* __restrict__ bZ){
    __shared__ float sk[8], sz[8];
    int j = blockIdx.x, t = threadIdx.x;
    float ck = 0.f, cz = 0.f;
    for (int k=t;k<HH;k+=256){
        float wkv = WK[j*HH+k];
        float wzv = WZ[j*HH+k];
        float c = g_c[k];
        float sv = g_s[k];
        ck = fmaf(wkv, c, ck);
        cz = fmaf(wzv, c, cz);
        g_Bt[k*1024 + j]       = __uint_as_float(cvt_tf32(wkv*sv));
        g_Bt[k*1024 + 512 + j] = __uint_as_float(cvt_tf32(wzv*sv));
    }
    #pragma unroll
    for (int o=16;o;o>>=1){ ck += __shfl_xor_sync(~0u,ck,o); cz += __shfl_xor_sync(~0u,cz,o); }
    if ((t&31)==0){ sk[t>>5]=ck; sz[t>>5]=cz; }
    __syncthreads();
    if (t==0){
        float a=0.f,b2=0.f;
        #pragma unroll
        for (int i=0;i<8;i++){ a+=sk[i]; b2+=sz[i]; }
        g_bcat[j]     = bK[j] + a;
        g_bcat[512+j] = bZ[j] + b2;
    }
}

// ---------------- 7) projections: tf32 GEMM, PN=128, 2 CTAs/SM ----------------
__global__ void __launch_bounds__(256,2) k_pmma(){
    extern __shared__ float smem[];
    float* As[2] = { smem, smem + PM*APAD };
    float* Bs[2] = { smem + 2*PM*APAD, smem + 2*PM*APAD + PK*BPAD };
    uint32_t sA[2], sB[2];
    sA[0] = (uint32_t)__cvta_generic_to_shared(As[0]);
    sA[1] = (uint32_t)__cvta_generic_to_shared(As[1]);
    sB[0] = (uint32_t)__cvta_generic_to_shared(Bs[0]);
    sB[1] = (uint32_t)__cvta_generic_to_shared(Bs[1]);

    int tid = threadIdx.x;
    int wid = tid>>5, lane = tid&31;
    int g = lane>>2, tig = lane&3;
    int wm = wid & 1, wn = wid >> 1;   // 2 x 4 warps; warp tile 64m x 32n
    int m0 = blockIdx.x * PM;
    int nb = blockIdx.y * PN;

    const float* Ag = g_o  + (size_t)m0*HH;
    const float* Bg = g_Bt + nb;

    float acc[4][4][4];
    #pragma unroll
    for (int mt=0;mt<4;mt++)
        #pragma unroll
        for (int nt=0;nt<4;nt++)
            #pragma unroll
            for (int i=0;i<4;i++) acc[mt][nt][i]=0.f;

    auto stage = [&](int c, int buf){
        #pragma unroll
        for (int i=0;i<4;i++){
            int u = i*256 + tid;          // A: 128 rows x 8 segs
            int row = u>>3, seg = u&7;
            cp16(sA[buf] + (row*APAD + seg*4)*4, Ag + row*HH + c*PK + seg*4);
        }
        #pragma unroll
        for (int i=0;i<4;i++){
            int u = i*256 + tid;          // B: 32 rows x 32 segs (128 floats/row)
            int row = u>>5, seg = u&31;
            cp16(sB[buf] + (row*BPAD + seg*4)*4, Bg + (size_t)(c*PK + row)*1024 + seg*4);
        }
        asm volatile("cp.async.commit_group;");
    };

    stage(0, 0);
    #pragma unroll 1
    for (int c=0;c<16;c++){
        int buf = c & 1;
        if (c < 15) stage(c+1, buf^1);
        if (c < 15) asm volatile("cp.async.wait_group 1;");
        else        asm volatile("cp.async.wait_group 0;");
        __syncthreads();

        #pragma unroll
        for (int k8=0;k8<4;k8++){
            int kk = k8*8;
            uint32_t a[4][4];
            #pragma unroll
            for (int mt=0;mt<4;mt++){
                const float* ap = &As[buf][(wm*64 + mt*16 + g)*APAD + kk + tig];
                a[mt][0] = __float_as_uint(ap[0]);
                a[mt][1] = __float_as_uint(ap[8*APAD]);
                a[mt][2] = __float_as_uint(ap[4]);
                a[mt][3] = __float_as_uint(ap[8*APAD+4]);
            }
            uint32_t b[4][2];
            #pragma unroll
            for (int nt=0;nt<4;nt++){
                const float* bp = &Bs[buf][(kk + tig)*BPAD + wn*32 + nt*8 + g];
                b[nt][0] = __float_as_uint(bp[0]);
                b[nt][1] = __float_as_uint(bp[4*BPAD]);
            }
            #pragma unroll
            for (int mt=0;mt<4;mt++)
                #pragma unroll
                for (int nt=0;nt<4;nt++)
                    mma_tf32(acc[mt][nt], a[mt], b[nt]);
        }
        __syncthreads();
    }

    bool isZ = (nb >= 512);
    #pragma unroll
    for (int mt=0;mt<4;mt++){
        int r0 = m0 + wm*64 + mt*16 + g;
        #pragma unroll
        for (int nt=0;nt<4;nt++){
            int n = nb + wn*32 + nt*8 + 2*tig;
            float b0v = g_bcat[n], b1v = g_bcat[n+1];
            float v00 = acc[mt][nt][0]+b0v, v01 = acc[mt][nt][1]+b1v;
            float v10 = acc[mt][nt][2]+b0v, v11 = acc[mt][nt][3]+b1v;
            if (isZ){
                int nz = n - 512;
                float2 lo = make_float2(tanh_a(v00), tanh_a(v01));
                float2 hi = make_float2(tanh_a(v10), tanh_a(v11));
                *(float2*)&g_z[(size_t)r0*HH + nz]     = lo;
                *(float2*)&g_z[(size_t)(r0+8)*HH + nz] = hi;
            } else {
                *(float2*)&g_xK[(size_t)r0*HH + n]     = make_float2(v00, v01);
                *(float2*)&g_xK[(size_t)(r0+8)*HH + n] = make_float2(v10, v11);
            }
        }
    }
}

// ---------------- 8) head ----------------
__global__ void __launch_bounds__(512) k_head(const float* __restrict__ bng, const float* __restrict__ bnb,
                                              const float* __restrict__ lng, const float* __restrict__ lnb,
                                              const float* __restrict__ Wc,  const float* __restrict__ bc,
                                              float* __restrict__ out){
    __shared__ float red[16];
    __shared__ float hsm[HH];
    __shared__ float lg[CC];
    int b = blockIdx.x, tid = threadIdx.x;

    float v = g_o[(b*TT + TT-1)*HH + tid];
    float y = (v - g_mean[tid])*g_rstd[tid]*bng[tid] + bnb[tid];

    float t1 = y;
    #pragma unroll
    for (int o=16;o;o>>=1) t1 += __shfl_xor_sync(~0u,t1,o);
    if ((tid&31)==0) red[tid>>5] = t1;
    __syncthreads();
    float mu = 0.f;
    #pragma unroll
    for (int i=0;i<16;i++) mu += red[i];
    mu *= (1.f/HH);
    __syncthreads();

    float d = y - mu;
    float t2 = d*d;
    #pragma unroll
    for (int o=16;o;o>>=1) t2 += __shfl_xor_sync(~0u,t2,o);
    if ((tid&31)==0) red[tid>>5] = t2;
    __syncthreads();
    float var = 0.f;
    #pragma unroll
    for (int i=0;i<16;i++) var += red[i];
    var *= (1.f/HH);
    float rs = rsqrtf(var + EPSF);
    hsm[tid] = d*rs*lng[tid] + lnb[tid];
    __syncthreads();

    int w = tid>>5, l = tid&31;
    if (w < CC){
        float p = 0.f;
        for (int k=l;k<HH;k+=32) p = fmaf(hsm[k], Wc[w*HH + k], p);
        #pragma unroll
        for (int o=16;o;o>>=1) p += __shfl_xor_sync(~0u,p,o);
        if (l==0) lg[w] = p + bc[w];
    }
    __syncthreads();
    if (tid==0){
        float mx = lg[0];
        #pragma unroll
        for (int c=1;c<CC;c++) mx = fmaxf(mx, lg[c]);
        float sm = 0.f;
        #pragma unroll
        for (int c=0;c<CC;c++) sm += expf(lg[c]-mx);
        float lse = mx + logf(sm);
        #pragma unroll
        for (int c=0;c<CC;c++) out[b*CC + c] = lg[c] - lse;
    }
}

// ---------------- launch sequence ----------------
extern "C" void kernel_launch(void* const* d_in, const int* in_sizes, int n_in,
                              void* d_out, int out_size){
    const float* x      = (const float*)d_in[0];
    const float* inln_g = (const float*)d_in[1];
    const float* inln_b = (const float*)d_in[2];
    const float* WxK1   = (const float*)d_in[3];
    const float* bxK1   = (const float*)d_in[4];
    const float* Wxz1   = (const float*)d_in[5];
    const float* bxz1   = (const float*)d_in[6];
    const float* WhK1   = (const float*)d_in[7];
    const float* bhK1   = (const float*)d_in[8];
    const float* bn1_g  = (const float*)d_in[9];
    const float* bn1_b  = (const float*)d_in[10];
    const float* WxK2   = (const float*)d_in[11];
    const float* bxK2   = (const float*)d_in[12];
    const float* Wxz2   = (const float*)d_in[13];
    const float* bxz2   = (const float*)d_in[14];
    const float* WhK2   = (const float*)d_in[15];
    const float* bhK2   = (const float*)d_in[16];
    const float* bn2_g  = (const float*)d_in[17];
    const float* bn2_b  = (const float*)d_in[18];
    const float* cln_g  = (const float*)d_in[19];
    const float* cln_b  = (const float*)d_in[20];
    const float* Wc     = (const float*)d_in[21];
    const float* bc     = (const float*)d_in[22];
    float* out = (float*)d_out;

    static int inited = 0;
    if (!inited){
        cudaFuncSetAttribute(k_pmma,  cudaFuncAttributeMaxDynamicSharedMemorySize, PMMA_SMEM);
        cudaFuncSetAttribute(k_recur, cudaFuncAttributeMaxDynamicSharedMemorySize, RSMEM2);
        inited = 1;
    }

    dim3 mg(BT/PM, 1024/PN);

    // input LN + layer-1 projections
    k_ln   <<<BT/256, 256>>>(x, inln_g, inln_b);
    k_proj1<<<BT/64, 512>>>(WxK1, bxK1, Wxz1, bxz1);

    // layer 1
    k_packW2  <<<256, 512>>>(WhK1);
    k_recur   <<<BB/8, 256, RSMEM2>>>(bhK1);
    k_statsfin<<<1, 512>>>(bn1_g, bn1_b);
    k_fold2   <<<HH, 256>>>(WxK2, bxK2, Wxz2, bxz2);

    // layer 2
    k_pmma    <<<mg, 256, PMMA_SMEM>>>();
    k_packW2  <<<256, 512>>>(WhK2);
    k_recur   <<<BB/8, 256, RSMEM2>>>(bhK2);
    k_statsfin<<<1, 512>>>(bn2_g, bn2_b);
    k_fold2   <<<HH, 256>>>(WxK2, bxK2, Wxz2, bxz2);

    // layer 3 (shared weights; g_W2hi/g_W2lo still hold packed WhK2)
    k_pmma    <<<mg, 256, PMMA_SMEM>>>();
    k_recur   <<<BB/8, 256, RSMEM2>>>(bhK2);
    k_statsfin<<<1, 512>>>(bn2_g, bn2_b);

    // head
    k_head <<<BB, 512>>>(bn2_g, bn2_b, cln_g, cln_b, Wc, bc, out);
}